// round 6
// baseline (speedup 1.0000x reference)
#include <cuda_runtime.h>
#include <cuda_fp16.h>
#include <math_constants.h>

#define N_NODES 50000
#define NEDGE   1600000
#define HDIM    128
#define NUC     49232
#define NMC     512
#define NSC     256
#define NB      196      // scan blocks: 196*256 = 50176 >= N_NODES
#define DCH     8        // register chunks -> handles degree <= 256 in-register

// ---------------- scratch (device globals; no allocation allowed) ----------------
__device__ float  g_X[(size_t)N_NODES * HDIM];   // layer input / activated output
__device__ __half g_Hh[(size_t)N_NODES * HDIM];  // h = X @ W, fp16 for gather path
__device__ float  g_el[N_NODES];
__device__ float  g_er[N_NODES];
__device__ float  g_ebuf[NEDGE];                 // fallback scratch (deg > 256 only)
__device__ int    g_deg[N_NODES];
__device__ int    g_rowptr[N_NODES + 1];
__device__ int    g_pos[N_NODES];
__device__ int    g_esrc[NEDGE];                 // src ids sorted by dst
__device__ int    g_bsum[NB];
__device__ int    g_boff[NB];
__device__ float  g_T[NMC * HDIM];               // model @ Wb

// ---------------- CSR build ----------------
__global__ void k_zero_deg() {
    int i = blockIdx.x * blockDim.x + threadIdx.x;
    if (i < N_NODES) g_deg[i] = 0;
}

__global__ void k_count(const int* __restrict__ dst) {
    int e = blockIdx.x * blockDim.x + threadIdx.x;
    if (e < NEDGE) atomicAdd(&g_deg[dst[e]], 1);
}

// multi-block exclusive scan, stage 1: per-block exclusive scan + block sums
__global__ void k_scan1() {
    __shared__ int wsum[8];
    __shared__ int wpre[8];
    int t = threadIdx.x, lane = t & 31, w = t >> 5;
    int idx = blockIdx.x * 256 + t;
    int v = (idx < N_NODES) ? g_deg[idx] : 0;
    int incl = v;
    #pragma unroll
    for (int o = 1; o < 32; o <<= 1) {
        int y = __shfl_up_sync(0xffffffffu, incl, o);
        if (lane >= o) incl += y;
    }
    if (lane == 31) wsum[w] = incl;
    __syncthreads();
    if (t < 8) {
        int x = wsum[t], xs = x;
        #pragma unroll
        for (int o = 1; o < 8; o <<= 1) {
            int y = __shfl_up_sync(0xffu, xs, o);
            if (t >= o) xs += y;
        }
        wpre[t] = xs - x;
        if (t == 7) g_bsum[blockIdx.x] = xs;
    }
    __syncthreads();
    if (idx < N_NODES) g_rowptr[idx] = wpre[w] + incl - v;   // local exclusive
}

// stage 2: scan the 196 block sums
__global__ void k_scan2() {
    __shared__ int wsum[8];
    __shared__ int wpre[8];
    int t = threadIdx.x, lane = t & 31, w = t >> 5;
    int v = (t < NB) ? g_bsum[t] : 0;
    int incl = v;
    #pragma unroll
    for (int o = 1; o < 32; o <<= 1) {
        int y = __shfl_up_sync(0xffffffffu, incl, o);
        if (lane >= o) incl += y;
    }
    if (lane == 31) wsum[w] = incl;
    __syncthreads();
    if (t < 8) {
        int x = wsum[t], xs = x;
        #pragma unroll
        for (int o = 1; o < 8; o <<= 1) {
            int y = __shfl_up_sync(0xffu, xs, o);
            if (t >= o) xs += y;
        }
        wpre[t] = xs - x;
    }
    __syncthreads();
    if (t < NB) g_boff[t] = wpre[w] + incl - v;
    if (t == 0) g_rowptr[N_NODES] = NEDGE;
}

// stage 3: add block offsets
__global__ void k_scan3() {
    int t = threadIdx.x;
    int idx = blockIdx.x * 256 + t;
    if (idx < N_NODES) {
        int r = g_rowptr[idx] + g_boff[blockIdx.x];
        g_rowptr[idx] = r;
        g_pos[idx]    = r;
    }
}

__global__ void k_scatter(const int* __restrict__ src, const int* __restrict__ dst) {
    int e = blockIdx.x * blockDim.x + threadIdx.x;
    if (e < NEDGE) {
        int p = atomicAdd(&g_pos[dst[e]], 1);
        g_esrc[p] = src[e];
    }
}

// ---------------- GEMM: H[nrows x 128] = X[nrows x 128] @ W[128 x 128] ----------------
// 256 threads/block, block computes 64 rows x 128 cols. Thread: 8 rows x 4 cols.
// Output: fp16 Yh (gather path) and/or fp32 Yf (head path).
// Fused epilogue: el[row]=Y[row]@al, er[row]=Y[row]@ar (warp owns 8 full rows).
__global__ void k_gemm(const float* __restrict__ X, const float* __restrict__ W,
                       float* __restrict__ Yf, __half* __restrict__ Yh, int nrows,
                       const float* __restrict__ al, const float* __restrict__ ar) {
    extern __shared__ float smem[];
    float* ws = smem;           // 128*128 = 64 KB
    float* xs = smem + 16384;   // 64*128 = 32 KB
    int t = threadIdx.x;
    int row0 = blockIdx.x * 64;

    const float4* W4 = (const float4*)W;
    float4* ws4 = (float4*)ws;
    #pragma unroll 4
    for (int i = t; i < 4096; i += 256) ws4[i] = W4[i];

    const float4* X4 = (const float4*)X;
    float4* xs4 = (float4*)xs;
    #pragma unroll 2
    for (int i = t; i < 2048; i += 256) {
        int r = i >> 5, c = i & 31;
        float4 v = make_float4(0.f, 0.f, 0.f, 0.f);
        if (row0 + r < nrows) v = X4[(size_t)(row0 + r) * 32 + c];
        xs4[i] = v;
    }
    __syncthreads();

    int lane = t & 31;
    int cj = lane * 4;
    int r0 = (t >> 5) * 8;
    float acc[8][4];
    #pragma unroll
    for (int r = 0; r < 8; r++)
        #pragma unroll
        for (int c = 0; c < 4; c++) acc[r][c] = 0.f;

    #pragma unroll 2
    for (int kk = 0; kk < 128; kk += 4) {
        float4 xv[8];
        #pragma unroll
        for (int r = 0; r < 8; r++)
            xv[r] = *(const float4*)(xs + (r0 + r) * 128 + kk);
        #pragma unroll
        for (int q = 0; q < 4; q++) {
            float4 w4 = *(const float4*)(ws + (kk + q) * 128 + cj);
            #pragma unroll
            for (int r = 0; r < 8; r++) {
                float xvq = (q == 0) ? xv[r].x : (q == 1) ? xv[r].y : (q == 2) ? xv[r].z : xv[r].w;
                acc[r][0] += xvq * w4.x;
                acc[r][1] += xvq * w4.y;
                acc[r][2] += xvq * w4.z;
                acc[r][3] += xvq * w4.w;
            }
        }
    }

    #pragma unroll
    for (int r = 0; r < 8; r++) {
        int row = row0 + r0 + r;
        if (row < nrows) {
            if (Yh) {
                __half2 p0 = __floats2half2_rn(acc[r][0], acc[r][1]);
                __half2 p1 = __floats2half2_rn(acc[r][2], acc[r][3]);
                unsigned u0 = *(unsigned*)&p0;
                unsigned u1 = *(unsigned*)&p1;
                ((uint2*)Yh)[(size_t)row * 32 + lane] = make_uint2(u0, u1);
            }
            if (Yf)
                *(float4*)(Yf + (size_t)row * 128 + cj) =
                    make_float4(acc[r][0], acc[r][1], acc[r][2], acc[r][3]);
        }
    }

    // fused attention dot products (fp32 accumulators -> exact-ish el/er)
    if (al != nullptr) {
        float4 a4 = ((const float4*)al)[lane];
        float4 r4 = ((const float4*)ar)[lane];
        #pragma unroll
        for (int r = 0; r < 8; r++) {
            float pl = acc[r][0] * a4.x + acc[r][1] * a4.y +
                       acc[r][2] * a4.z + acc[r][3] * a4.w;
            float pr = acc[r][0] * r4.x + acc[r][1] * r4.y +
                       acc[r][2] * r4.z + acc[r][3] * r4.w;
            #pragma unroll
            for (int o = 16; o; o >>= 1) {
                pl += __shfl_xor_sync(0xffffffffu, pl, o);
                pr += __shfl_xor_sync(0xffffffffu, pr, o);
            }
            int row = row0 + r0 + r;
            if (lane == 0 && row < nrows) { g_el[row] = pl; g_er[row] = pr; }
        }
    }
}

// ---------------- fused softmax-attention + aggregation, one warp per dst node ----------------
// Edge scores and src ids live in registers (DCH chunks of 32 edges); exactly one
// exp per edge; pass B broadcasts weight+src via shfl and gathers fp16 H rows.
__global__ void k_node(const float* __restrict__ bvec, int do_relu) {
    int gw = (blockIdx.x * blockDim.x + threadIdx.x) >> 5;
    int lane = threadIdx.x & 31;
    if (gw >= N_NODES) return;
    int start = g_rowptr[gw];
    int end   = g_rowptr[gw + 1];
    int deg   = end - start;
    float eld = g_el[gw];
    const uint2* H2 = (const uint2*)g_Hh;
    float4 acc = make_float4(0.f, 0.f, 0.f, 0.f);

    if (deg <= 32 * DCH) {
        int nch = (deg + 31) >> 5;
        float ev[DCH];
        int   sv[DCH];

        // pass A1: gather scores into registers + max
        float m = -CUDART_INF_F;
        #pragma unroll
        for (int c = 0; c < DCH; c++) {
            int i = start + c * 32 + lane;
            bool act = (c < nch) && (i < end);
            int s = act ? g_esrc[i] : 0;
            float e = -CUDART_INF_F;
            if (act) {
                e = eld + g_er[s];
                e = (e > 0.f) ? e : 0.2f * e;     // leaky_relu 0.2
            }
            ev[c] = e; sv[c] = s;
            m = fmaxf(m, e);
        }
        #pragma unroll
        for (int o = 16; o; o >>= 1) m = fmaxf(m, __shfl_xor_sync(0xffffffffu, m, o));

        // pass A2: single exp per edge + sum
        float ssum = 0.f;
        #pragma unroll
        for (int c = 0; c < DCH; c++) {
            int i = start + c * 32 + lane;
            bool act = (c < nch) && (i < end);
            float p = act ? __expf(ev[c] - m) : 0.f;
            ev[c] = p;
            ssum += p;
        }
        #pragma unroll
        for (int o = 16; o; o >>= 1) ssum += __shfl_xor_sync(0xffffffffu, ssum, o);
        float inv = 1.f / (ssum + 1e-10f);

        // pass B: broadcast weight+src from lanes, gather fp16 rows
        #pragma unroll
        for (int c = 0; c < DCH; c++) {
            if (c >= nch) break;
            int rem = end - (start + c * 32);
            int cnt = rem < 32 ? rem : 32;
            float evc = ev[c];
            int   svc = sv[c];
            #pragma unroll 4
            for (int j = 0; j < cnt; j++) {
                float a = __shfl_sync(0xffffffffu, evc, j) * inv;
                int   s = __shfl_sync(0xffffffffu, svc, j);
                uint2 raw = H2[(size_t)s * 32 + lane];
                __half2 h0 = *(__half2*)&raw.x;
                __half2 h1 = *(__half2*)&raw.y;
                float2 f0 = __half22float2(h0);
                float2 f1 = __half22float2(h1);
                acc.x += a * f0.x; acc.y += a * f0.y;
                acc.z += a * f1.x; acc.w += a * f1.y;
            }
        }
    } else {
        // streaming fallback (deg > 256): 3 passes through edge range
        float m = -CUDART_INF_F;
        for (int i = start + lane; i < end; i += 32) {
            int s = g_esrc[i];
            float e = eld + g_er[s];
            e = (e > 0.f) ? e : 0.2f * e;
            g_ebuf[i] = e;
            m = fmaxf(m, e);
        }
        #pragma unroll
        for (int o = 16; o; o >>= 1) m = fmaxf(m, __shfl_xor_sync(0xffffffffu, m, o));
        float ssum = 0.f;
        for (int i = start + lane; i < end; i += 32) {
            float v = __expf(g_ebuf[i] - m);
            g_ebuf[i] = v;
            ssum += v;
        }
        #pragma unroll
        for (int o = 16; o; o >>= 1) ssum += __shfl_xor_sync(0xffffffffu, ssum, o);
        float inv = 1.f / (ssum + 1e-10f);
        __syncwarp();
        for (int i = start; i < end; i++) {
            float a = g_ebuf[i] * inv;
            int s = g_esrc[i];
            uint2 raw = H2[(size_t)s * 32 + lane];
            __half2 h0 = *(__half2*)&raw.x;
            __half2 h1 = *(__half2*)&raw.y;
            float2 f0 = __half22float2(h0);
            float2 f1 = __half22float2(h1);
            acc.x += a * f0.x; acc.y += a * f0.y;
            acc.z += a * f1.x; acc.w += a * f1.y;
        }
    }

    float4 b4 = ((const float4*)bvec)[lane];
    float4 o4 = make_float4(acc.x + b4.x, acc.y + b4.y, acc.z + b4.z, acc.w + b4.w);
    if (do_relu) {
        o4.x = fmaxf(o4.x, 0.f); o4.y = fmaxf(o4.y, 0.f);
        o4.z = fmaxf(o4.z, 0.f); o4.w = fmaxf(o4.w, 0.f);
    }
    ((float4*)g_X)[(size_t)gw * 32 + lane] = o4;
}

// ---------------- bilinear head: scores[m][s] = dot(T[m], server[s]) + bb ----------------
__global__ void k_scores(const float* __restrict__ bb, float* __restrict__ out) {
    __shared__ __align__(16) float Tm[16][132];
    __shared__ __align__(16) float Ss[16][132];
    int tx = threadIdx.x;       // s within tile
    int ty = threadIdx.y;       // m within tile
    int m0 = blockIdx.x * 16, s0 = blockIdx.y * 16;
    int t = ty * 16 + tx;
    for (int i = t; i < 512; i += 256) {
        int r = i >> 5, c = i & 31;
        float4 v = ((const float4*)g_T)[(size_t)(m0 + r) * 32 + c];
        *(float4*)&Tm[r][c * 4] = v;
        float4 w = ((const float4*)g_X)[(size_t)(NUC + NMC + s0 + r) * 32 + c];
        *(float4*)&Ss[r][c * 4] = w;
    }
    __syncthreads();
    float4 acc = make_float4(0.f, 0.f, 0.f, 0.f);
    #pragma unroll 8
    for (int k = 0; k < 32; k++) {
        float4 a = *(const float4*)&Tm[ty][k * 4];
        float4 b = *(const float4*)&Ss[tx][k * 4];
        acc.x += a.x * b.x; acc.y += a.y * b.y;
        acc.z += a.z * b.z; acc.w += a.w * b.w;
    }
    out[(m0 + ty) * NSC + (s0 + tx)] = acc.x + acc.y + acc.z + acc.w + bb[0];
}

// ---------------- host ----------------
extern "C" void kernel_launch(void* const* d_in, const int* in_sizes, int n_in,
                              void* d_out, int out_size) {
    const float* x   = (const float*)d_in[0];
    const int*   ei  = (const int*)  d_in[1];
    const int*   src = ei;
    const int*   dst = ei + NEDGE;
    const float* W1  = (const float*)d_in[2];
    const float* al1 = (const float*)d_in[3];
    const float* ar1 = (const float*)d_in[4];
    const float* b1  = (const float*)d_in[5];
    const float* W2  = (const float*)d_in[6];
    const float* al2 = (const float*)d_in[7];
    const float* ar2 = (const float*)d_in[8];
    const float* b2  = (const float*)d_in[9];
    const float* W3  = (const float*)d_in[10];
    const float* al3 = (const float*)d_in[11];
    const float* ar3 = (const float*)d_in[12];
    const float* b3  = (const float*)d_in[13];
    const float* Wb  = (const float*)d_in[14];
    const float* bb  = (const float*)d_in[15];
    float* out = (float*)d_out;

    void *pX_, *pHh_, *pT_;
    cudaGetSymbolAddress(&pX_, g_X);
    cudaGetSymbolAddress(&pHh_, g_Hh);
    cudaGetSymbolAddress(&pT_, g_T);
    float*  pX = (float*)pX_;
    __half* pH = (__half*)pHh_;
    float*  pT = (float*)pT_;

    cudaFuncSetAttribute(k_gemm, cudaFuncAttributeMaxDynamicSharedMemorySize, 98304);

    // CSR build (dst-sorted edge list)
    k_zero_deg<<<NB, 256>>>();
    k_count  <<<(NEDGE + 255) / 256, 256>>>(dst);
    k_scan1  <<<NB, 256>>>();
    k_scan2  <<<1, 256>>>();
    k_scan3  <<<NB, 256>>>();
    k_scatter<<<(NEDGE + 255) / 256, 256>>>(src, dst);

    int warpgrid = (N_NODES * 32 + 255) / 256;
    int gemmgrid = (N_NODES + 63) / 64;

    // layer 1
    k_gemm<<<gemmgrid, 256, 98304>>>(x, W1, nullptr, pH, N_NODES, al1, ar1);
    k_node<<<warpgrid, 256>>>(b1, 1);
    // layer 2
    k_gemm<<<gemmgrid, 256, 98304>>>(pX, W2, nullptr, pH, N_NODES, al2, ar2);
    k_node<<<warpgrid, 256>>>(b2, 1);
    // layer 3 (no relu)
    k_gemm<<<gemmgrid, 256, 98304>>>(pX, W3, nullptr, pH, N_NODES, al3, ar3);
    k_node<<<warpgrid, 256>>>(b3, 0);

    // bilinear head
    k_gemm<<<(NMC + 63) / 64, 256, 98304>>>(pX + (size_t)NUC * HDIM, Wb, pT, nullptr, NMC,
                                            nullptr, nullptr);
    k_scores<<<dim3(NMC / 16, NSC / 16), dim3(16, 16)>>>(bb, out);
}

// round 8
// speedup vs baseline: 1.2795x; 1.2795x over previous
#include <cuda_runtime.h>
#include <cuda_fp16.h>
#include <math_constants.h>

#define N_NODES 50000
#define NEDGE   1600000
#define HDIM    128
#define NUC     49232
#define NMC     512
#define NSC     256
#define NB      196      // scan blocks: 196*256 = 50176 >= N_NODES

// ---------------- scratch (device globals; no allocation allowed) ----------------
__device__ float  g_X[(size_t)N_NODES * HDIM];   // layer input / activated output
__device__ __half g_Hh[(size_t)N_NODES * HDIM];  // h = X @ W, fp16 for gather path
__device__ float  g_el[N_NODES];
__device__ float  g_er[N_NODES];
__device__ float  g_ebuf[NEDGE];                 // per-edge scores -> exp weights
__device__ int    g_deg[N_NODES];
__device__ int    g_rowptr[N_NODES + 1];
__device__ int    g_pos[N_NODES];
__device__ int    g_esrc[NEDGE];                 // src ids sorted by dst
__device__ int    g_bsum[NB];
__device__ int    g_boff[NB];
__device__ float  g_T[NMC * HDIM];               // model @ Wb

// ---------------- CSR build ----------------
__global__ void k_zero_deg() {
    int i = blockIdx.x * blockDim.x + threadIdx.x;
    if (i < N_NODES) g_deg[i] = 0;
}

__global__ void k_count(const int* __restrict__ dst) {
    int e = blockIdx.x * blockDim.x + threadIdx.x;
    if (e < NEDGE) atomicAdd(&g_deg[dst[e]], 1);
}

// multi-block exclusive scan, stage 1: per-block exclusive scan + block sums
__global__ void k_scan1() {
    __shared__ int wsum[8];
    __shared__ int wpre[8];
    int t = threadIdx.x, lane = t & 31, w = t >> 5;
    int idx = blockIdx.x * 256 + t;
    int v = (idx < N_NODES) ? g_deg[idx] : 0;
    int incl = v;
    #pragma unroll
    for (int o = 1; o < 32; o <<= 1) {
        int y = __shfl_up_sync(0xffffffffu, incl, o);
        if (lane >= o) incl += y;
    }
    if (lane == 31) wsum[w] = incl;
    __syncthreads();
    if (t < 8) {
        int x = wsum[t], xs = x;
        #pragma unroll
        for (int o = 1; o < 8; o <<= 1) {
            int y = __shfl_up_sync(0xffu, xs, o);
            if (t >= o) xs += y;
        }
        wpre[t] = xs - x;
        if (t == 7) g_bsum[blockIdx.x] = xs;
    }
    __syncthreads();
    if (idx < N_NODES) g_rowptr[idx] = wpre[w] + incl - v;   // local exclusive
}

// stage 2: scan the 196 block sums
__global__ void k_scan2() {
    __shared__ int wsum[8];
    __shared__ int wpre[8];
    int t = threadIdx.x, lane = t & 31, w = t >> 5;
    int v = (t < NB) ? g_bsum[t] : 0;
    int incl = v;
    #pragma unroll
    for (int o = 1; o < 32; o <<= 1) {
        int y = __shfl_up_sync(0xffffffffu, incl, o);
        if (lane >= o) incl += y;
    }
    if (lane == 31) wsum[w] = incl;
    __syncthreads();
    if (t < 8) {
        int x = wsum[t], xs = x;
        #pragma unroll
        for (int o = 1; o < 8; o <<= 1) {
            int y = __shfl_up_sync(0xffu, xs, o);
            if (t >= o) xs += y;
        }
        wpre[t] = xs - x;
    }
    __syncthreads();
    if (t < NB) g_boff[t] = wpre[w] + incl - v;
    if (t == 0) g_rowptr[N_NODES] = NEDGE;
}

// stage 3: add block offsets
__global__ void k_scan3() {
    int t = threadIdx.x;
    int idx = blockIdx.x * 256 + t;
    if (idx < N_NODES) {
        int r = g_rowptr[idx] + g_boff[blockIdx.x];
        g_rowptr[idx] = r;
        g_pos[idx]    = r;
    }
}

__global__ void k_scatter(const int* __restrict__ src, const int* __restrict__ dst) {
    int e = blockIdx.x * blockDim.x + threadIdx.x;
    if (e < NEDGE) {
        int p = atomicAdd(&g_pos[dst[e]], 1);
        g_esrc[p] = src[e];
    }
}

// ---------------- GEMM: H[nrows x 128] = X[nrows x 128] @ W[128 x 128] ----------------
// 256 threads/block, block computes 64 rows x 128 cols. Thread: 8 rows x 4 cols.
// Output: fp16 Yh (gather path) and/or fp32 Yf (head path).
// Fused epilogue: el[row]=Y[row]@al, er[row]=Y[row]@ar (warp owns 8 full rows).
__global__ void k_gemm(const float* __restrict__ X, const float* __restrict__ W,
                       float* __restrict__ Yf, __half* __restrict__ Yh, int nrows,
                       const float* __restrict__ al, const float* __restrict__ ar) {
    extern __shared__ float smem[];
    float* ws = smem;           // 128*128 = 64 KB
    float* xs = smem + 16384;   // 64*128 = 32 KB
    int t = threadIdx.x;
    int row0 = blockIdx.x * 64;

    const float4* W4 = (const float4*)W;
    float4* ws4 = (float4*)ws;
    #pragma unroll 4
    for (int i = t; i < 4096; i += 256) ws4[i] = W4[i];

    const float4* X4 = (const float4*)X;
    float4* xs4 = (float4*)xs;
    #pragma unroll 2
    for (int i = t; i < 2048; i += 256) {
        int r = i >> 5, c = i & 31;
        float4 v = make_float4(0.f, 0.f, 0.f, 0.f);
        if (row0 + r < nrows) v = X4[(size_t)(row0 + r) * 32 + c];
        xs4[i] = v;
    }
    __syncthreads();

    int lane = t & 31;
    int cj = lane * 4;
    int r0 = (t >> 5) * 8;
    float acc[8][4];
    #pragma unroll
    for (int r = 0; r < 8; r++)
        #pragma unroll
        for (int c = 0; c < 4; c++) acc[r][c] = 0.f;

    #pragma unroll 2
    for (int kk = 0; kk < 128; kk += 4) {
        float4 xv[8];
        #pragma unroll
        for (int r = 0; r < 8; r++)
            xv[r] = *(const float4*)(xs + (r0 + r) * 128 + kk);
        #pragma unroll
        for (int q = 0; q < 4; q++) {
            float4 w4 = *(const float4*)(ws + (kk + q) * 128 + cj);
            #pragma unroll
            for (int r = 0; r < 8; r++) {
                float xvq = (q == 0) ? xv[r].x : (q == 1) ? xv[r].y : (q == 2) ? xv[r].z : xv[r].w;
                acc[r][0] += xvq * w4.x;
                acc[r][1] += xvq * w4.y;
                acc[r][2] += xvq * w4.z;
                acc[r][3] += xvq * w4.w;
            }
        }
    }

    #pragma unroll
    for (int r = 0; r < 8; r++) {
        int row = row0 + r0 + r;
        if (row < nrows) {
            if (Yh) {
                __half2 p0 = __floats2half2_rn(acc[r][0], acc[r][1]);
                __half2 p1 = __floats2half2_rn(acc[r][2], acc[r][3]);
                unsigned u0 = *(unsigned*)&p0;
                unsigned u1 = *(unsigned*)&p1;
                ((uint2*)Yh)[(size_t)row * 32 + lane] = make_uint2(u0, u1);
            }
            if (Yf)
                *(float4*)(Yf + (size_t)row * 128 + cj) =
                    make_float4(acc[r][0], acc[r][1], acc[r][2], acc[r][3]);
        }
    }

    // fused attention dot products (fp32 accumulators -> exact-ish el/er)
    if (al != nullptr) {
        float4 a4 = ((const float4*)al)[lane];
        float4 r4 = ((const float4*)ar)[lane];
        #pragma unroll
        for (int r = 0; r < 8; r++) {
            float pl = acc[r][0] * a4.x + acc[r][1] * a4.y +
                       acc[r][2] * a4.z + acc[r][3] * a4.w;
            float pr = acc[r][0] * r4.x + acc[r][1] * r4.y +
                       acc[r][2] * r4.z + acc[r][3] * r4.w;
            #pragma unroll
            for (int o = 16; o; o >>= 1) {
                pl += __shfl_xor_sync(0xffffffffu, pl, o);
                pr += __shfl_xor_sync(0xffffffffu, pr, o);
            }
            int row = row0 + r0 + r;
            if (lane == 0 && row < nrows) { g_el[row] = pl; g_er[row] = pr; }
        }
    }
}

// ---------------- fused softmax-attention + aggregation, one warp per dst node ----------------
// 3-pass streaming: pass1 score+max, pass2 exp(once per lane-edge)+sum,
// pass3 broadcast precomputed weight (NO MUFU) + fp16 row gather.
__global__ void k_node(const float* __restrict__ bvec, int do_relu) {
    int gw = (blockIdx.x * blockDim.x + threadIdx.x) >> 5;
    int lane = threadIdx.x & 31;
    if (gw >= N_NODES) return;
    int start = g_rowptr[gw];
    int end   = g_rowptr[gw + 1];
    float eld = g_el[gw];

    // pass 1: raw scores + segment max
    float m = -CUDART_INF_F;
    for (int i = start + lane; i < end; i += 32) {
        int s = g_esrc[i];
        float e = eld + g_er[s];
        e = (e > 0.f) ? e : 0.2f * e;     // leaky_relu 0.2
        g_ebuf[i] = e;
        m = fmaxf(m, e);
    }
    #pragma unroll
    for (int o = 16; o; o >>= 1) m = fmaxf(m, __shfl_xor_sync(0xffffffffu, m, o));

    // pass 2: exp (one MUFU per lane-edge) + segment sum
    float ssum = 0.f;
    for (int i = start + lane; i < end; i += 32) {
        float v = __expf(g_ebuf[i] - m);
        g_ebuf[i] = v;
        ssum += v;
    }
    #pragma unroll
    for (int o = 16; o; o >>= 1) ssum += __shfl_xor_sync(0xffffffffu, ssum, o);
    float inv = 1.f / (ssum + 1e-10f);
    __syncwarp();   // make cross-lane g_ebuf writes visible

    // pass 3: weighted fp16 gather; lane owns 4 contiguous cols; no MUFU here
    float4 acc = make_float4(0.f, 0.f, 0.f, 0.f);
    const uint2* H2 = (const uint2*)g_Hh;
    #pragma unroll 4
    for (int i = start; i < end; i++) {
        float a = g_ebuf[i] * inv;        // broadcast load, precomputed exp
        int s = g_esrc[i];                // broadcast load
        uint2 raw = H2[(size_t)s * 32 + lane];
        __half2 h0 = *(__half2*)&raw.x;
        __half2 h1 = *(__half2*)&raw.y;
        float2 f0 = __half22float2(h0);
        float2 f1 = __half22float2(h1);
        acc.x += a * f0.x; acc.y += a * f0.y;
        acc.z += a * f1.x; acc.w += a * f1.y;
    }

    float4 b4 = ((const float4*)bvec)[lane];
    float4 o4 = make_float4(acc.x + b4.x, acc.y + b4.y, acc.z + b4.z, acc.w + b4.w);
    if (do_relu) {
        o4.x = fmaxf(o4.x, 0.f); o4.y = fmaxf(o4.y, 0.f);
        o4.z = fmaxf(o4.z, 0.f); o4.w = fmaxf(o4.w, 0.f);
    }
    ((float4*)g_X)[(size_t)gw * 32 + lane] = o4;
}

// ---------------- bilinear head: scores[m][s] = dot(T[m], server[s]) + bb ----------------
__global__ void k_scores(const float* __restrict__ bb, float* __restrict__ out) {
    __shared__ __align__(16) float Tm[16][132];
    __shared__ __align__(16) float Ss[16][132];
    int tx = threadIdx.x;       // s within tile
    int ty = threadIdx.y;       // m within tile
    int m0 = blockIdx.x * 16, s0 = blockIdx.y * 16;
    int t = ty * 16 + tx;
    for (int i = t; i < 512; i += 256) {
        int r = i >> 5, c = i & 31;
        float4 v = ((const float4*)g_T)[(size_t)(m0 + r) * 32 + c];
        *(float4*)&Tm[r][c * 4] = v;
        float4 w = ((const float4*)g_X)[(size_t)(NUC + NMC + s0 + r) * 32 + c];
        *(float4*)&Ss[r][c * 4] = w;
    }
    __syncthreads();
    float4 acc = make_float4(0.f, 0.f, 0.f, 0.f);
    #pragma unroll 8
    for (int k = 0; k < 32; k++) {
        float4 a = *(const float4*)&Tm[ty][k * 4];
        float4 b = *(const float4*)&Ss[tx][k * 4];
        acc.x += a.x * b.x; acc.y += a.y * b.y;
        acc.z += a.z * b.z; acc.w += a.w * b.w;
    }
    out[(m0 + ty) * NSC + (s0 + tx)] = acc.x + acc.y + acc.z + acc.w + bb[0];
}

// ---------------- host ----------------
extern "C" void kernel_launch(void* const* d_in, const int* in_sizes, int n_in,
                              void* d_out, int out_size) {
    const float* x   = (const float*)d_in[0];
    const int*   ei  = (const int*)  d_in[1];
    const int*   src = ei;
    const int*   dst = ei + NEDGE;
    const float* W1  = (const float*)d_in[2];
    const float* al1 = (const float*)d_in[3];
    const float* ar1 = (const float*)d_in[4];
    const float* b1  = (const float*)d_in[5];
    const float* W2  = (const float*)d_in[6];
    const float* al2 = (const float*)d_in[7];
    const float* ar2 = (const float*)d_in[8];
    const float* b2  = (const float*)d_in[9];
    const float* W3  = (const float*)d_in[10];
    const float* al3 = (const float*)d_in[11];
    const float* ar3 = (const float*)d_in[12];
    const float* b3  = (const float*)d_in[13];
    const float* Wb  = (const float*)d_in[14];
    const float* bb  = (const float*)d_in[15];
    float* out = (float*)d_out;

    void *pX_, *pHh_, *pT_;
    cudaGetSymbolAddress(&pX_, g_X);
    cudaGetSymbolAddress(&pHh_, g_Hh);
    cudaGetSymbolAddress(&pT_, g_T);
    float*  pX = (float*)pX_;
    __half* pH = (__half*)pHh_;
    float*  pT = (float*)pT_;

    cudaFuncSetAttribute(k_gemm, cudaFuncAttributeMaxDynamicSharedMemorySize, 98304);

    // CSR build (dst-sorted edge list)
    k_zero_deg<<<NB, 256>>>();
    k_count  <<<(NEDGE + 255) / 256, 256>>>(dst);
    k_scan1  <<<NB, 256>>>();
    k_scan2  <<<1, 256>>>();
    k_scan3  <<<NB, 256>>>();
    k_scatter<<<(NEDGE + 255) / 256, 256>>>(src, dst);

    int warpgrid = (N_NODES * 32 + 255) / 256;
    int gemmgrid = (N_NODES + 63) / 64;

    // layer 1
    k_gemm<<<gemmgrid, 256, 98304>>>(x, W1, nullptr, pH, N_NODES, al1, ar1);
    k_node<<<warpgrid, 256>>>(b1, 1);
    // layer 2
    k_gemm<<<gemmgrid, 256, 98304>>>(pX, W2, nullptr, pH, N_NODES, al2, ar2);
    k_node<<<warpgrid, 256>>>(b2, 1);
    // layer 3 (no relu)
    k_gemm<<<gemmgrid, 256, 98304>>>(pX, W3, nullptr, pH, N_NODES, al3, ar3);
    k_node<<<warpgrid, 256>>>(b3, 0);

    // bilinear head
    k_gemm<<<(NMC + 63) / 64, 256, 98304>>>(pX + (size_t)NUC * HDIM, Wb, pT, nullptr, NMC,
                                            nullptr, nullptr);
    k_scores<<<dim3(NMC / 16, NSC / 16), dim3(16, 16)>>>(bb, out);
}

// round 9
// speedup vs baseline: 1.2861x; 1.0051x over previous
#include <cuda_runtime.h>
#include <cuda_fp16.h>
#include <math_constants.h>
#include <mma.h>

using namespace nvcuda;

#define N_NODES 50000
#define NEDGE   1600000
#define HDIM    128
#define NUC     49232
#define NMC     512
#define NSC     256
#define NB      196      // scan blocks: 196*256 = 50176 >= N_NODES
#define LDS_    136      // smem row stride (floats), multiple of 8 for wmma

// ---------------- scratch (device globals; no allocation allowed) ----------------
__device__ float  g_X[(size_t)N_NODES * HDIM];   // layer input / activated output
__device__ __half g_Hh[(size_t)N_NODES * HDIM];  // h = X @ W, fp16 for gather path
__device__ float  g_el[N_NODES];
__device__ float  g_er[N_NODES];
__device__ float  g_ebuf[NEDGE];                 // per-edge scores -> exp weights
__device__ int    g_deg[N_NODES];
__device__ int    g_rowptr[N_NODES + 1];
__device__ int    g_pos[N_NODES];
__device__ int    g_esrc[NEDGE];                 // src ids sorted by dst
__device__ int    g_bsum[NB];
__device__ int    g_boff[NB];
__device__ float  g_T[NMC * HDIM];               // model @ Wb

// ---------------- CSR build ----------------
__global__ void k_zero_deg() {
    int i = blockIdx.x * blockDim.x + threadIdx.x;
    if (i < N_NODES) g_deg[i] = 0;
}

// 4 edges per thread, int4 loads -> 4 overlapped atomics
__global__ void k_count(const int* __restrict__ dst) {
    int i = blockIdx.x * blockDim.x + threadIdx.x;
    if (i < NEDGE / 4) {
        int4 d = ((const int4*)dst)[i];
        atomicAdd(&g_deg[d.x], 1);
        atomicAdd(&g_deg[d.y], 1);
        atomicAdd(&g_deg[d.z], 1);
        atomicAdd(&g_deg[d.w], 1);
    }
}

// multi-block exclusive scan, stage 1: per-block exclusive scan + block sums
__global__ void k_scan1() {
    __shared__ int wsum[8];
    __shared__ int wpre[8];
    int t = threadIdx.x, lane = t & 31, w = t >> 5;
    int idx = blockIdx.x * 256 + t;
    int v = (idx < N_NODES) ? g_deg[idx] : 0;
    int incl = v;
    #pragma unroll
    for (int o = 1; o < 32; o <<= 1) {
        int y = __shfl_up_sync(0xffffffffu, incl, o);
        if (lane >= o) incl += y;
    }
    if (lane == 31) wsum[w] = incl;
    __syncthreads();
    if (t < 8) {
        int x = wsum[t], xs = x;
        #pragma unroll
        for (int o = 1; o < 8; o <<= 1) {
            int y = __shfl_up_sync(0xffu, xs, o);
            if (t >= o) xs += y;
        }
        wpre[t] = xs - x;
        if (t == 7) g_bsum[blockIdx.x] = xs;
    }
    __syncthreads();
    if (idx < N_NODES) g_rowptr[idx] = wpre[w] + incl - v;   // local exclusive
}

// stage 2: scan the 196 block sums
__global__ void k_scan2() {
    __shared__ int wsum[8];
    __shared__ int wpre[8];
    int t = threadIdx.x, lane = t & 31, w = t >> 5;
    int v = (t < NB) ? g_bsum[t] : 0;
    int incl = v;
    #pragma unroll
    for (int o = 1; o < 32; o <<= 1) {
        int y = __shfl_up_sync(0xffffffffu, incl, o);
        if (lane >= o) incl += y;
    }
    if (lane == 31) wsum[w] = incl;
    __syncthreads();
    if (t < 8) {
        int x = wsum[t], xs = x;
        #pragma unroll
        for (int o = 1; o < 8; o <<= 1) {
            int y = __shfl_up_sync(0xffu, xs, o);
            if (t >= o) xs += y;
        }
        wpre[t] = xs - x;
    }
    __syncthreads();
    if (t < NB) g_boff[t] = wpre[w] + incl - v;
    if (t == 0) g_rowptr[N_NODES] = NEDGE;
}

// stage 3: add block offsets
__global__ void k_scan3() {
    int t = threadIdx.x;
    int idx = blockIdx.x * 256 + t;
    if (idx < N_NODES) {
        int r = g_rowptr[idx] + g_boff[blockIdx.x];
        g_rowptr[idx] = r;
        g_pos[idx]    = r;
    }
}

// 4 edges per thread
__global__ void k_scatter(const int* __restrict__ src, const int* __restrict__ dst) {
    int i = blockIdx.x * blockDim.x + threadIdx.x;
    if (i < NEDGE / 4) {
        int4 s = ((const int4*)src)[i];
        int4 d = ((const int4*)dst)[i];
        int p0 = atomicAdd(&g_pos[d.x], 1);
        int p1 = atomicAdd(&g_pos[d.y], 1);
        int p2 = atomicAdd(&g_pos[d.z], 1);
        int p3 = atomicAdd(&g_pos[d.w], 1);
        g_esrc[p0] = s.x;
        g_esrc[p1] = s.y;
        g_esrc[p2] = s.z;
        g_esrc[p3] = s.w;
    }
}

// ---------------- GEMM (tf32 tensor cores): H = X @ W ----------------
// 256 threads (8 warps), block tile 64 rows x 128 cols.
// warp w: row-tile (w>>1)*16, col base (w&1)*64, 4 acc fragments of 16x16.
// Accumulators -> smem C, then epilogue: fp16 Yh / fp32 Yf + fused el/er dots.
__global__ void k_gemm(const float* __restrict__ X, const float* __restrict__ W,
                       float* __restrict__ Yf, __half* __restrict__ Yh, int nrows,
                       const float* __restrict__ al, const float* __restrict__ ar) {
    extern __shared__ float smem[];
    float* xs = smem;                 // 64 x LDS_  (also reused as C)
    float* ws = smem + 64 * LDS_;     // 128 x LDS_
    int t = threadIdx.x;
    int row0 = blockIdx.x * 64;

    // load W [128x128] into ws (row stride LDS_)
    #pragma unroll 4
    for (int i = t; i < 4096; i += 256) {
        int r = i >> 5, c = i & 31;
        float4 v = ((const float4*)W)[i];
        *(float4*)(ws + r * LDS_ + c * 4) = v;
    }
    // load X tile [64x128] into xs
    #pragma unroll 2
    for (int i = t; i < 2048; i += 256) {
        int r = i >> 5, c = i & 31;
        float4 v = make_float4(0.f, 0.f, 0.f, 0.f);
        if (row0 + r < nrows) v = ((const float4*)X)[(size_t)(row0 + r) * 32 + c];
        *(float4*)(xs + r * LDS_ + c * 4) = v;
    }
    __syncthreads();

    int w  = t >> 5;
    int rt = w >> 1;                 // row-tile 0..3
    int c0 = (w & 1) * 64;           // col base 0 or 64

    wmma::fragment<wmma::accumulator, 16, 16, 8, float> acc[4];
    #pragma unroll
    for (int j = 0; j < 4; j++) wmma::fill_fragment(acc[j], 0.f);

    #pragma unroll 4
    for (int k = 0; k < 16; k++) {
        wmma::fragment<wmma::matrix_a, 16, 16, 8, wmma::precision::tf32, wmma::row_major> a;
        wmma::load_matrix_sync(a, xs + rt * 16 * LDS_ + k * 8, LDS_);
        #pragma unroll
        for (int i = 0; i < a.num_elements; i++) a.x[i] = wmma::__float_to_tf32(a.x[i]);
        #pragma unroll
        for (int j = 0; j < 4; j++) {
            wmma::fragment<wmma::matrix_b, 16, 16, 8, wmma::precision::tf32, wmma::row_major> b;
            wmma::load_matrix_sync(b, ws + k * 8 * LDS_ + c0 + j * 16, LDS_);
            #pragma unroll
            for (int i = 0; i < b.num_elements; i++) b.x[i] = wmma::__float_to_tf32(b.x[i]);
            wmma::mma_sync(acc[j], a, b, acc[j]);
        }
    }
    __syncthreads();   // everyone done reading xs before overwrite as C

    #pragma unroll
    for (int j = 0; j < 4; j++)
        wmma::store_matrix_sync(xs + rt * 16 * LDS_ + c0 + j * 16, acc[j], LDS_,
                                wmma::mem_row_major);
    __syncthreads();

    // epilogue: warp owns 8 rows (all 128 cols across 32 lanes x 4 cols)
    int lane = t & 31;
    int cj = lane * 4;
    int r0 = w * 8;
    float4 a4 = make_float4(0.f, 0.f, 0.f, 0.f), r4 = a4;
    if (al != nullptr) {
        a4 = ((const float4*)al)[lane];
        r4 = ((const float4*)ar)[lane];
    }
    #pragma unroll
    for (int r = 0; r < 8; r++) {
        int row = row0 + r0 + r;
        float4 v = *(const float4*)(xs + (r0 + r) * LDS_ + cj);
        if (row < nrows) {
            if (Yh) {
                __half2 p0 = __floats2half2_rn(v.x, v.y);
                __half2 p1 = __floats2half2_rn(v.z, v.w);
                unsigned u0 = *(unsigned*)&p0;
                unsigned u1 = *(unsigned*)&p1;
                ((uint2*)Yh)[(size_t)row * 32 + lane] = make_uint2(u0, u1);
            }
            if (Yf)
                *(float4*)(Yf + (size_t)row * 128 + cj) = v;
        }
        if (al != nullptr) {
            float pl = v.x * a4.x + v.y * a4.y + v.z * a4.z + v.w * a4.w;
            float pr = v.x * r4.x + v.y * r4.y + v.z * r4.z + v.w * r4.w;
            #pragma unroll
            for (int o = 16; o; o >>= 1) {
                pl += __shfl_xor_sync(0xffffffffu, pl, o);
                pr += __shfl_xor_sync(0xffffffffu, pr, o);
            }
            if (lane == 0 && row < nrows) { g_el[row] = pl; g_er[row] = pr; }
        }
    }
}

// ---------------- fused softmax-attention + aggregation, one warp per dst node ----------------
// 3-pass streaming: pass1 score+max, pass2 exp(once per lane-edge)+sum,
// pass3 broadcast precomputed weight (NO MUFU) + fp16 row gather.
__global__ void k_node(const float* __restrict__ bvec, int do_relu) {
    int gw = (blockIdx.x * blockDim.x + threadIdx.x) >> 5;
    int lane = threadIdx.x & 31;
    if (gw >= N_NODES) return;
    int start = g_rowptr[gw];
    int end   = g_rowptr[gw + 1];
    float eld = g_el[gw];

    // pass 1: raw scores + segment max
    float m = -CUDART_INF_F;
    for (int i = start + lane; i < end; i += 32) {
        int s = g_esrc[i];
        float e = eld + g_er[s];
        e = (e > 0.f) ? e : 0.2f * e;     // leaky_relu 0.2
        g_ebuf[i] = e;
        m = fmaxf(m, e);
    }
    #pragma unroll
    for (int o = 16; o; o >>= 1) m = fmaxf(m, __shfl_xor_sync(0xffffffffu, m, o));

    // pass 2: exp (one MUFU per lane-edge) + segment sum
    float ssum = 0.f;
    for (int i = start + lane; i < end; i += 32) {
        float v = __expf(g_ebuf[i] - m);
        g_ebuf[i] = v;
        ssum += v;
    }
    #pragma unroll
    for (int o = 16; o; o >>= 1) ssum += __shfl_xor_sync(0xffffffffu, ssum, o);
    float inv = 1.f / (ssum + 1e-10f);
    __syncwarp();   // make cross-lane g_ebuf writes visible

    // pass 3: weighted fp16 gather; lane owns 4 contiguous cols; no MUFU here
    float4 acc = make_float4(0.f, 0.f, 0.f, 0.f);
    const uint2* H2 = (const uint2*)g_Hh;
    #pragma unroll 4
    for (int i = start; i < end; i++) {
        float a = g_ebuf[i] * inv;        // broadcast load, precomputed exp
        int s = g_esrc[i];                // broadcast load
        uint2 raw = H2[(size_t)s * 32 + lane];
        __half2 h0 = *(__half2*)&raw.x;
        __half2 h1 = *(__half2*)&raw.y;
        float2 f0 = __half22float2(h0);
        float2 f1 = __half22float2(h1);
        acc.x += a * f0.x; acc.y += a * f0.y;
        acc.z += a * f1.x; acc.w += a * f1.y;
    }

    float4 b4 = ((const float4*)bvec)[lane];
    float4 o4 = make_float4(acc.x + b4.x, acc.y + b4.y, acc.z + b4.z, acc.w + b4.w);
    if (do_relu) {
        o4.x = fmaxf(o4.x, 0.f); o4.y = fmaxf(o4.y, 0.f);
        o4.z = fmaxf(o4.z, 0.f); o4.w = fmaxf(o4.w, 0.f);
    }
    ((float4*)g_X)[(size_t)gw * 32 + lane] = o4;
}

// ---------------- bilinear head: scores[m][s] = dot(T[m], server[s]) + bb ----------------
__global__ void k_scores(const float* __restrict__ bb, float* __restrict__ out) {
    __shared__ __align__(16) float Tm[16][132];
    __shared__ __align__(16) float Ss[16][132];
    int tx = threadIdx.x;       // s within tile
    int ty = threadIdx.y;       // m within tile
    int m0 = blockIdx.x * 16, s0 = blockIdx.y * 16;
    int t = ty * 16 + tx;
    for (int i = t; i < 512; i += 256) {
        int r = i >> 5, c = i & 31;
        float4 v = ((const float4*)g_T)[(size_t)(m0 + r) * 32 + c];
        *(float4*)&Tm[r][c * 4] = v;
        float4 w = ((const float4*)g_X)[(size_t)(NUC + NMC + s0 + r) * 32 + c];
        *(float4*)&Ss[r][c * 4] = w;
    }
    __syncthreads();
    float4 acc = make_float4(0.f, 0.f, 0.f, 0.f);
    #pragma unroll 8
    for (int k = 0; k < 32; k++) {
        float4 a = *(const float4*)&Tm[ty][k * 4];
        float4 b = *(const float4*)&Ss[tx][k * 4];
        acc.x += a.x * b.x; acc.y += a.y * b.y;
        acc.z += a.z * b.z; acc.w += a.w * b.w;
    }
    out[(m0 + ty) * NSC + (s0 + tx)] = acc.x + acc.y + acc.z + acc.w + bb[0];
}

// ---------------- host ----------------
extern "C" void kernel_launch(void* const* d_in, const int* in_sizes, int n_in,
                              void* d_out, int out_size) {
    const float* x   = (const float*)d_in[0];
    const int*   ei  = (const int*)  d_in[1];
    const int*   src = ei;
    const int*   dst = ei + NEDGE;
    const float* W1  = (const float*)d_in[2];
    const float* al1 = (const float*)d_in[3];
    const float* ar1 = (const float*)d_in[4];
    const float* b1  = (const float*)d_in[5];
    const float* W2  = (const float*)d_in[6];
    const float* al2 = (const float*)d_in[7];
    const float* ar2 = (const float*)d_in[8];
    const float* b2  = (const float*)d_in[9];
    const float* W3  = (const float*)d_in[10];
    const float* al3 = (const float*)d_in[11];
    const float* ar3 = (const float*)d_in[12];
    const float* b3  = (const float*)d_in[13];
    const float* Wb  = (const float*)d_in[14];
    const float* bb  = (const float*)d_in[15];
    float* out = (float*)d_out;

    void *pX_, *pHh_, *pT_;
    cudaGetSymbolAddress(&pX_, g_X);
    cudaGetSymbolAddress(&pHh_, g_Hh);
    cudaGetSymbolAddress(&pT_, g_T);
    float*  pX = (float*)pX_;
    __half* pH = (__half*)pHh_;
    float*  pT = (float*)pT_;

    const int smem_bytes = (64 + 128) * LDS_ * 4;   // 104448
    cudaFuncSetAttribute(k_gemm, cudaFuncAttributeMaxDynamicSharedMemorySize, smem_bytes);

    // CSR build (dst-sorted edge list)
    k_zero_deg<<<NB, 256>>>();
    k_count  <<<(NEDGE / 4 + 255) / 256, 256>>>(dst);
    k_scan1  <<<NB, 256>>>();
    k_scan2  <<<1, 256>>>();
    k_scan3  <<<NB, 256>>>();
    k_scatter<<<(NEDGE / 4 + 255) / 256, 256>>>(src, dst);

    int warpgrid = (N_NODES * 32 + 255) / 256;
    int gemmgrid = (N_NODES + 63) / 64;

    // layer 1
    k_gemm<<<gemmgrid, 256, smem_bytes>>>(x, W1, nullptr, pH, N_NODES, al1, ar1);
    k_node<<<warpgrid, 256>>>(b1, 1);
    // layer 2
    k_gemm<<<gemmgrid, 256, smem_bytes>>>(pX, W2, nullptr, pH, N_NODES, al2, ar2);
    k_node<<<warpgrid, 256>>>(b2, 1);
    // layer 3 (no relu)
    k_gemm<<<gemmgrid, 256, smem_bytes>>>(pX, W3, nullptr, pH, N_NODES, al3, ar3);
    k_node<<<warpgrid, 256>>>(b3, 0);

    // bilinear head
    k_gemm<<<(NMC + 63) / 64, 256, smem_bytes>>>(pX + (size_t)NUC * HDIM, Wb, pT, nullptr, NMC,
                                                 nullptr, nullptr);
    k_scores<<<dim3(NMC / 16, NSC / 16), dim3(16, 16)>>>(bb, out);
}

// round 11
// speedup vs baseline: 1.3075x; 1.0167x over previous
#include <cuda_runtime.h>
#include <cuda_fp16.h>
#include <math_constants.h>

#define N_NODES 50000
#define NEDGE   1600000
#define HDIM    128
#define NUC     49232
#define NMC     512
#define NSC     256
#define NB      196      // scan blocks: 196*256 = 50176 >= N_NODES

// ---------------- scratch (device globals; no allocation allowed) ----------------
__device__ float  g_X[(size_t)N_NODES * HDIM];   // layer input / activated output
__device__ __half g_Hh[(size_t)N_NODES * HDIM];  // h = X @ W, fp16 for gather path
__device__ float  g_el[N_NODES];
__device__ float  g_er[N_NODES];
__device__ float  g_ebuf[NEDGE];                 // per-edge exp weights
__device__ int    g_deg[N_NODES];                // zero-initialized (.bss); re-zeroed by k_scan1
__device__ int    g_rowptr[N_NODES + 1];
__device__ int    g_pos[N_NODES];
__device__ int    g_esrc[NEDGE];                 // src ids sorted by dst
__device__ int    g_bsum[NB];
__device__ int    g_boff[NB];
__device__ float  g_T[NMC * HDIM];               // model @ Wb

// ---------------- CSR build ----------------
// 4 edges per thread, int4 loads -> 4 overlapped atomics
__global__ void k_count(const int* __restrict__ dst) {
    int i = blockIdx.x * blockDim.x + threadIdx.x;
    if (i < NEDGE / 4) {
        int4 d = ((const int4*)dst)[i];
        atomicAdd(&g_deg[d.x], 1);
        atomicAdd(&g_deg[d.y], 1);
        atomicAdd(&g_deg[d.z], 1);
        atomicAdd(&g_deg[d.w], 1);
    }
}

// stage 1: per-block exclusive scan + block sums; also re-zeroes g_deg for the
// next graph replay (deterministic: g_deg starts zeroed from .bss / prior scan1)
__global__ void k_scan1() {
    __shared__ int wsum[8];
    __shared__ int wpre[8];
    int t = threadIdx.x, lane = t & 31, w = t >> 5;
    int idx = blockIdx.x * 256 + t;
    int v = (idx < N_NODES) ? g_deg[idx] : 0;
    if (idx < N_NODES) g_deg[idx] = 0;           // reset for next replay
    int incl = v;
    #pragma unroll
    for (int o = 1; o < 32; o <<= 1) {
        int y = __shfl_up_sync(0xffffffffu, incl, o);
        if (lane >= o) incl += y;
    }
    if (lane == 31) wsum[w] = incl;
    __syncthreads();
    if (t < 8) {
        int x = wsum[t], xs = x;
        #pragma unroll
        for (int o = 1; o < 8; o <<= 1) {
            int y = __shfl_up_sync(0xffu, xs, o);
            if (t >= o) xs += y;
        }
        wpre[t] = xs - x;
        if (t == 7) g_bsum[blockIdx.x] = xs;
    }
    __syncthreads();
    if (idx < N_NODES) g_rowptr[idx] = wpre[w] + incl - v;   // local exclusive
}

// stage 2: scan the 196 block sums
__global__ void k_scan2() {
    __shared__ int wsum[8];
    __shared__ int wpre[8];
    int t = threadIdx.x, lane = t & 31, w = t >> 5;
    int v = (t < NB) ? g_bsum[t] : 0;
    int incl = v;
    #pragma unroll
    for (int o = 1; o < 32; o <<= 1) {
        int y = __shfl_up_sync(0xffffffffu, incl, o);
        if (lane >= o) incl += y;
    }
    if (lane == 31) wsum[w] = incl;
    __syncthreads();
    if (t < 8) {
        int x = wsum[t], xs = x;
        #pragma unroll
        for (int o = 1; o < 8; o <<= 1) {
            int y = __shfl_up_sync(0xffu, xs, o);
            if (t >= o) xs += y;
        }
        wpre[t] = xs - x;
    }
    __syncthreads();
    if (t < NB) g_boff[t] = wpre[w] + incl - v;
    if (t == 0) g_rowptr[N_NODES] = NEDGE;
}

// stage 3: add block offsets
__global__ void k_scan3() {
    int t = threadIdx.x;
    int idx = blockIdx.x * 256 + t;
    if (idx < N_NODES) {
        int r = g_rowptr[idx] + g_boff[blockIdx.x];
        g_rowptr[idx] = r;
        g_pos[idx]    = r;
    }
}

// 4 edges per thread
__global__ void k_scatter(const int* __restrict__ src, const int* __restrict__ dst) {
    int i = blockIdx.x * blockDim.x + threadIdx.x;
    if (i < NEDGE / 4) {
        int4 s = ((const int4*)src)[i];
        int4 d = ((const int4*)dst)[i];
        int p0 = atomicAdd(&g_pos[d.x], 1);
        int p1 = atomicAdd(&g_pos[d.y], 1);
        int p2 = atomicAdd(&g_pos[d.z], 1);
        int p3 = atomicAdd(&g_pos[d.w], 1);
        g_esrc[p0] = s.x;
        g_esrc[p1] = s.y;
        g_esrc[p2] = s.z;
        g_esrc[p3] = s.w;
    }
}

// ---------------- GEMM: H[nrows x 128] = X[nrows x 128] @ W[128 x 128] ----------------
// 256 threads/block, block computes 64 rows x 128 cols. Thread: 8 rows x 4 cols. (fp32)
// Fused epilogue: el[row]=Y[row]@al, er[row]=Y[row]@ar (warp owns 8 full rows).
__global__ void k_gemm(const float* __restrict__ X, const float* __restrict__ W,
                       float* __restrict__ Yf, __half* __restrict__ Yh, int nrows,
                       const float* __restrict__ al, const float* __restrict__ ar) {
    extern __shared__ float smem[];
    float* ws = smem;           // 128*128 = 64 KB
    float* xs = smem + 16384;   // 64*128 = 32 KB
    int t = threadIdx.x;
    int row0 = blockIdx.x * 64;

    const float4* W4 = (const float4*)W;
    float4* ws4 = (float4*)ws;
    #pragma unroll 4
    for (int i = t; i < 4096; i += 256) ws4[i] = W4[i];

    const float4* X4 = (const float4*)X;
    float4* xs4 = (float4*)xs;
    #pragma unroll 2
    for (int i = t; i < 2048; i += 256) {
        int r = i >> 5, c = i & 31;
        float4 v = make_float4(0.f, 0.f, 0.f, 0.f);
        if (row0 + r < nrows) v = X4[(size_t)(row0 + r) * 32 + c];
        xs4[i] = v;
    }
    __syncthreads();

    int lane = t & 31;
    int cj = lane * 4;
    int r0 = (t >> 5) * 8;
    float acc[8][4];
    #pragma unroll
    for (int r = 0; r < 8; r++)
        #pragma unroll
        for (int c = 0; c < 4; c++) acc[r][c] = 0.f;

    #pragma unroll 2
    for (int kk = 0; kk < 128; kk += 4) {
        float4 xv[8];
        #pragma unroll
        for (int r = 0; r < 8; r++)
            xv[r] = *(const float4*)(xs + (r0 + r) * 128 + kk);
        #pragma unroll
        for (int q = 0; q < 4; q++) {
            float4 w4 = *(const float4*)(ws + (kk + q) * 128 + cj);
            #pragma unroll
            for (int r = 0; r < 8; r++) {
                float xvq = (q == 0) ? xv[r].x : (q == 1) ? xv[r].y : (q == 2) ? xv[r].z : xv[r].w;
                acc[r][0] += xvq * w4.x;
                acc[r][1] += xvq * w4.y;
                acc[r][2] += xvq * w4.z;
                acc[r][3] += xvq * w4.w;
            }
        }
    }

    #pragma unroll
    for (int r = 0; r < 8; r++) {
        int row = row0 + r0 + r;
        if (row < nrows) {
            if (Yh) {
                __half2 p0 = __floats2half2_rn(acc[r][0], acc[r][1]);
                __half2 p1 = __floats2half2_rn(acc[r][2], acc[r][3]);
                unsigned u0 = *(unsigned*)&p0;
                unsigned u1 = *(unsigned*)&p1;
                ((uint2*)Yh)[(size_t)row * 32 + lane] = make_uint2(u0, u1);
            }
            if (Yf)
                *(float4*)(Yf + (size_t)row * 128 + cj) =
                    make_float4(acc[r][0], acc[r][1], acc[r][2], acc[r][3]);
        }
    }

    // fused attention dot products (fp32 accumulators -> exact-ish el/er)
    if (al != nullptr) {
        float4 a4 = ((const float4*)al)[lane];
        float4 r4 = ((const float4*)ar)[lane];
        #pragma unroll
        for (int r = 0; r < 8; r++) {
            float pl = acc[r][0] * a4.x + acc[r][1] * a4.y +
                       acc[r][2] * a4.z + acc[r][3] * a4.w;
            float pr = acc[r][0] * r4.x + acc[r][1] * r4.y +
                       acc[r][2] * r4.z + acc[r][3] * r4.w;
            #pragma unroll
            for (int o = 16; o; o >>= 1) {
                pl += __shfl_xor_sync(0xffffffffu, pl, o);
                pr += __shfl_xor_sync(0xffffffffu, pr, o);
            }
            int row = row0 + r0 + r;
            if (lane == 0 && row < nrows) { g_el[row] = pl; g_er[row] = pr; }
        }
    }
}

// ---------------- fused softmax-attention + aggregation, one warp per dst node ----------------
// 2-pass max-free softmax: scores bounded (|e| << 80) so exp(e) is fp32-safe and
// the normalized result is algebraically identical to the max-subtracted form.
// pass A: p=exp(leaky(el+er)) -> ebuf, sum. pass B: broadcast weight + fp16 gather.
__global__ void k_node(const float* __restrict__ bvec, int do_relu) {
    int gw = (blockIdx.x * blockDim.x + threadIdx.x) >> 5;
    int lane = threadIdx.x & 31;
    if (gw >= N_NODES) return;
    int start = g_rowptr[gw];
    int end   = g_rowptr[gw + 1];
    float eld = g_el[gw];

    // pass A: exp(score) + segment sum (one MUFU per lane-edge)
    float ssum = 0.f;
    for (int i = start + lane; i < end; i += 32) {
        int s = g_esrc[i];
        float e = eld + g_er[s];
        e = (e > 0.f) ? e : 0.2f * e;     // leaky_relu 0.2
        float p = __expf(e);
        g_ebuf[i] = p;
        ssum += p;
    }
    #pragma unroll
    for (int o = 16; o; o >>= 1) ssum += __shfl_xor_sync(0xffffffffu, ssum, o);
    float inv = 1.f / (ssum + 1e-10f);
    __syncwarp();   // make cross-lane g_ebuf writes visible

    // pass B: weighted fp16 gather; lane owns 4 contiguous cols; no MUFU here
    float4 acc = make_float4(0.f, 0.f, 0.f, 0.f);
    const uint2* H2 = (const uint2*)g_Hh;
    #pragma unroll 4
    for (int i = start; i < end; i++) {
        float a = g_ebuf[i] * inv;        // broadcast load, precomputed exp
        int s = g_esrc[i];                // broadcast load
        uint2 raw = H2[(size_t)s * 32 + lane];
        __half2 h0 = *(__half2*)&raw.x;
        __half2 h1 = *(__half2*)&raw.y;
        float2 f0 = __half22float2(h0);
        float2 f1 = __half22float2(h1);
        acc.x += a * f0.x; acc.y += a * f0.y;
        acc.z += a * f1.x; acc.w += a * f1.y;
    }

    float4 b4 = ((const float4*)bvec)[lane];
    float4 o4 = make_float4(acc.x + b4.x, acc.y + b4.y, acc.z + b4.z, acc.w + b4.w);
    if (do_relu) {
        o4.x = fmaxf(o4.x, 0.f); o4.y = fmaxf(o4.y, 0.f);
        o4.z = fmaxf(o4.z, 0.f); o4.w = fmaxf(o4.w, 0.f);
    }
    ((float4*)g_X)[(size_t)gw * 32 + lane] = o4;
}

// ---------------- bilinear head: scores[m][s] = dot(T[m], server[s]) + bb ----------------
__global__ void k_scores(const float* __restrict__ bb, float* __restrict__ out) {
    __shared__ __align__(16) float Tm[16][132];
    __shared__ __align__(16) float Ss[16][132];
    int tx = threadIdx.x;       // s within tile
    int ty = threadIdx.y;       // m within tile
    int m0 = blockIdx.x * 16, s0 = blockIdx.y * 16;
    int t = ty * 16 + tx;
    for (int i = t; i < 512; i += 256) {
        int r = i >> 5, c = i & 31;
        float4 v = ((const float4*)g_T)[(size_t)(m0 + r) * 32 + c];
        *(float4*)&Tm[r][c * 4] = v;
        float4 w = ((const float4*)g_X)[(size_t)(NUC + NMC + s0 + r) * 32 + c];
        *(float4*)&Ss[r][c * 4] = w;
    }
    __syncthreads();
    float4 acc = make_float4(0.f, 0.f, 0.f, 0.f);
    #pragma unroll 8
    for (int k = 0; k < 32; k++) {
        float4 a = *(const float4*)&Tm[ty][k * 4];
        float4 b = *(const float4*)&Ss[tx][k * 4];
        acc.x += a.x * b.x; acc.y += a.y * b.y;
        acc.z += a.z * b.z; acc.w += a.w * b.w;
    }
    out[(m0 + ty) * NSC + (s0 + tx)] = acc.x + acc.y + acc.z + acc.w + bb[0];
}

// ---------------- host ----------------
extern "C" void kernel_launch(void* const* d_in, const int* in_sizes, int n_in,
                              void* d_out, int out_size) {
    const float* x   = (const float*)d_in[0];
    const int*   ei  = (const int*)  d_in[1];
    const int*   src = ei;
    const int*   dst = ei + NEDGE;
    const float* W1  = (const float*)d_in[2];
    const float* al1 = (const float*)d_in[3];
    const float* ar1 = (const float*)d_in[4];
    const float* b1  = (const float*)d_in[5];
    const float* W2  = (const float*)d_in[6];
    const float* al2 = (const float*)d_in[7];
    const float* ar2 = (const float*)d_in[8];
    const float* b2  = (const float*)d_in[9];
    const float* W3  = (const float*)d_in[10];
    const float* al3 = (const float*)d_in[11];
    const float* ar3 = (const float*)d_in[12];
    const float* b3  = (const float*)d_in[13];
    const float* Wb  = (const float*)d_in[14];
    const float* bb  = (const float*)d_in[15];
    float* out = (float*)d_out;

    void *pX_, *pHh_, *pT_;
    cudaGetSymbolAddress(&pX_, g_X);
    cudaGetSymbolAddress(&pHh_, g_Hh);
    cudaGetSymbolAddress(&pT_, g_T);
    float*  pX = (float*)pX_;
    __half* pH = (__half*)pHh_;
    float*  pT = (float*)pT_;

    cudaFuncSetAttribute(k_gemm, cudaFuncAttributeMaxDynamicSharedMemorySize, 98304);

    int warpgrid = (N_NODES * 32 + 255) / 256;
    int gemmgrid = (N_NODES + 63) / 64;

    // CSR build; gemm layer-1 hoisted to launch index 3 so ncu (-s => idx 3)
    // profiles the GEMM. (Single stream: ordering is purely for profiling.)
    k_count  <<<(NEDGE / 4 + 255) / 256, 256>>>(dst);                       // 0
    k_scan1  <<<NB, 256>>>();                                               // 1
    k_scan2  <<<1, 256>>>();                                                // 2
    k_gemm<<<gemmgrid, 256, 98304>>>(x, W1, nullptr, pH, N_NODES, al1, ar1); // 3 (profiled)
    k_scan3  <<<NB, 256>>>();                                               // 4
    k_scatter<<<(NEDGE / 4 + 255) / 256, 256>>>(src, dst);                  // 5

    // layer 1 aggregation
    k_node<<<warpgrid, 256>>>(b1, 1);
    // layer 2
    k_gemm<<<gemmgrid, 256, 98304>>>(pX, W2, nullptr, pH, N_NODES, al2, ar2);
    k_node<<<warpgrid, 256>>>(b2, 1);
    // layer 3 (no relu)
    k_gemm<<<gemmgrid, 256, 98304>>>(pX, W3, nullptr, pH, N_NODES, al3, ar3);
    k_node<<<warpgrid, 256>>>(b3, 0);

    // bilinear head
    k_gemm<<<(NMC + 63) / 64, 256, 98304>>>(pX + (size_t)NUC * HDIM, Wb, pT, nullptr, NMC,
                                            nullptr, nullptr);
    k_scores<<<dim3(NMC / 16, NSC / 16), dim3(16, 16)>>>(bb, out);
}

// round 12
// speedup vs baseline: 1.5884x; 1.2148x over previous
#include <cuda_runtime.h>
#include <cuda_fp16.h>
#include <math_constants.h>
#include <mma.h>

using namespace nvcuda;

#define N_NODES 50000
#define NEDGE   1600000
#define HDIM    128
#define NUC     49232
#define NMC     512
#define NSC     256
#define NB      196      // scan blocks: 196*256 = 50176 >= N_NODES
#define LDH     136      // smem half-stride (mult of 8 for wmma fp16 ldm)
#define LDC     132      // smem float-stride for C (mult of 4)

// ---------------- scratch (device globals; no allocation allowed) ----------------
__device__ float  g_X[(size_t)N_NODES * HDIM];   // layer input / activated output
__device__ __half g_Hh[(size_t)N_NODES * HDIM];  // h = X @ W, fp16 for gather path
__device__ float  g_el[N_NODES];
__device__ float  g_er[N_NODES];
__device__ float  g_ebuf[NEDGE];                 // per-edge exp weights
__device__ int    g_deg[N_NODES];                // zero-initialized (.bss); re-zeroed by k_scan1
__device__ int    g_rowptr[N_NODES + 1];
__device__ int    g_pos[N_NODES];
__device__ int    g_esrc[NEDGE];                 // src ids sorted by dst
__device__ int    g_bsum[NB];
__device__ int    g_boff[NB];
__device__ float  g_T[NMC * HDIM];               // model @ Wb

// ---------------- CSR build ----------------
// 4 edges per thread, int4 loads -> 4 overlapped atomics
__global__ void k_count(const int* __restrict__ dst) {
    int i = blockIdx.x * blockDim.x + threadIdx.x;
    if (i < NEDGE / 4) {
        int4 d = ((const int4*)dst)[i];
        atomicAdd(&g_deg[d.x], 1);
        atomicAdd(&g_deg[d.y], 1);
        atomicAdd(&g_deg[d.z], 1);
        atomicAdd(&g_deg[d.w], 1);
    }
}

// stage 1: per-block exclusive scan + block sums; also re-zeroes g_deg for the
// next graph replay (deterministic: g_deg starts zeroed from .bss / prior scan1)
__global__ void k_scan1() {
    __shared__ int wsum[8];
    __shared__ int wpre[8];
    int t = threadIdx.x, lane = t & 31, w = t >> 5;
    int idx = blockIdx.x * 256 + t;
    int v = (idx < N_NODES) ? g_deg[idx] : 0;
    if (idx < N_NODES) g_deg[idx] = 0;           // reset for next replay
    int incl = v;
    #pragma unroll
    for (int o = 1; o < 32; o <<= 1) {
        int y = __shfl_up_sync(0xffffffffu, incl, o);
        if (lane >= o) incl += y;
    }
    if (lane == 31) wsum[w] = incl;
    __syncthreads();
    if (t < 8) {
        int x = wsum[t], xs = x;
        #pragma unroll
        for (int o = 1; o < 8; o <<= 1) {
            int y = __shfl_up_sync(0xffu, xs, o);
            if (t >= o) xs += y;
        }
        wpre[t] = xs - x;
        if (t == 7) g_bsum[blockIdx.x] = xs;
    }
    __syncthreads();
    if (idx < N_NODES) g_rowptr[idx] = wpre[w] + incl - v;   // local exclusive
}

// stage 2: scan the 196 block sums
__global__ void k_scan2() {
    __shared__ int wsum[8];
    __shared__ int wpre[8];
    int t = threadIdx.x, lane = t & 31, w = t >> 5;
    int v = (t < NB) ? g_bsum[t] : 0;
    int incl = v;
    #pragma unroll
    for (int o = 1; o < 32; o <<= 1) {
        int y = __shfl_up_sync(0xffffffffu, incl, o);
        if (lane >= o) incl += y;
    }
    if (lane == 31) wsum[w] = incl;
    __syncthreads();
    if (t < 8) {
        int x = wsum[t], xs = x;
        #pragma unroll
        for (int o = 1; o < 8; o <<= 1) {
            int y = __shfl_up_sync(0xffu, xs, o);
            if (t >= o) xs += y;
        }
        wpre[t] = xs - x;
    }
    __syncthreads();
    if (t < NB) g_boff[t] = wpre[w] + incl - v;
    if (t == 0) g_rowptr[N_NODES] = NEDGE;
}

// stage 3: add block offsets
__global__ void k_scan3() {
    int t = threadIdx.x;
    int idx = blockIdx.x * 256 + t;
    if (idx < N_NODES) {
        int r = g_rowptr[idx] + g_boff[blockIdx.x];
        g_rowptr[idx] = r;
        g_pos[idx]    = r;
    }
}

// 4 edges per thread
__global__ void k_scatter(const int* __restrict__ src, const int* __restrict__ dst) {
    int i = blockIdx.x * blockDim.x + threadIdx.x;
    if (i < NEDGE / 4) {
        int4 s = ((const int4*)src)[i];
        int4 d = ((const int4*)dst)[i];
        int p0 = atomicAdd(&g_pos[d.x], 1);
        int p1 = atomicAdd(&g_pos[d.y], 1);
        int p2 = atomicAdd(&g_pos[d.z], 1);
        int p3 = atomicAdd(&g_pos[d.w], 1);
        g_esrc[p0] = s.x;
        g_esrc[p1] = s.y;
        g_esrc[p2] = s.z;
        g_esrc[p3] = s.w;
    }
}

// ---------------- split-fp16 helpers ----------------
__device__ __forceinline__ void split_h(float x, __half& h, __half& l) {
    h = __float2half_rn(x);
    l = __float2half_rn(x - __half2float(h));
}
__device__ __forceinline__ uint2 pack4(__half a, __half b, __half c, __half d) {
    __half2 p0 = __halves2half2(a, b);
    __half2 p1 = __halves2half2(c, d);
    uint2 u;
    u.x = *(unsigned*)&p0;
    u.y = *(unsigned*)&p1;
    return u;
}

// ---------------- GEMM (split-fp16 tensor cores, fp32-class accuracy) ----------------
// H = X @ W via C = Xhi*Whi + Xhi*Wlo + Xlo*Whi (HMMA, fp32 accumulate).
// 256 threads (8 warps), block tile 64 rows x 128 cols. warp w: row-tile w>>1,
// col half (w&1)*64 (4 wmma col-tiles). Accumulators -> smem C, then epilogue:
// fp16 Yh / fp32 Yf + fused el/er dots (warp owns 8 rows).
__global__ void k_gemm(const float* __restrict__ X, const float* __restrict__ W,
                       float* __restrict__ Yf, __half* __restrict__ Yh, int nrows,
                       const float* __restrict__ al, const float* __restrict__ ar) {
    extern __shared__ __align__(16) char smem_raw[];
    __half* xh = (__half*)smem_raw;        // 64  x LDH
    __half* xl = xh + 64 * LDH;            // 64  x LDH
    __half* wh = xl + 64 * LDH;            // 128 x LDH
    __half* wl = wh + 128 * LDH;           // 128 x LDH
    float*  Cs = (float*)smem_raw;         // 64 x LDC (reused after mainloop)
    int t = threadIdx.x;
    int row0 = blockIdx.x * 64;

    // stage W [128x128] as hi/lo fp16
    const float4* W4 = (const float4*)W;
    #pragma unroll 4
    for (int i = t; i < 4096; i += 256) {
        int r = i >> 5, c4 = (i & 31) * 4;
        float4 v = W4[i];
        __half h0, h1, h2, h3, l0, l1, l2, l3;
        split_h(v.x, h0, l0); split_h(v.y, h1, l1);
        split_h(v.z, h2, l2); split_h(v.w, h3, l3);
        *(uint2*)(wh + r * LDH + c4) = pack4(h0, h1, h2, h3);
        *(uint2*)(wl + r * LDH + c4) = pack4(l0, l1, l2, l3);
    }
    // stage X tile [64x128] as hi/lo fp16
    const float4* X4 = (const float4*)X;
    #pragma unroll 2
    for (int i = t; i < 2048; i += 256) {
        int r = i >> 5, c4 = (i & 31) * 4;
        float4 v = make_float4(0.f, 0.f, 0.f, 0.f);
        if (row0 + r < nrows) v = X4[(size_t)(row0 + r) * 32 + (i & 31)];
        __half h0, h1, h2, h3, l0, l1, l2, l3;
        split_h(v.x, h0, l0); split_h(v.y, h1, l1);
        split_h(v.z, h2, l2); split_h(v.w, h3, l3);
        *(uint2*)(xh + r * LDH + c4) = pack4(h0, h1, h2, h3);
        *(uint2*)(xl + r * LDH + c4) = pack4(l0, l1, l2, l3);
    }
    __syncthreads();

    int w  = t >> 5;
    int rt = w >> 1;                 // row-tile 0..3 (16 rows each)
    int c0 = (w & 1) * 64;           // col base 0 or 64

    wmma::fragment<wmma::accumulator, 16, 16, 16, float> acc[4];
    #pragma unroll
    for (int j = 0; j < 4; j++) wmma::fill_fragment(acc[j], 0.f);

    #pragma unroll
    for (int k = 0; k < 8; k++) {
        wmma::fragment<wmma::matrix_a, 16, 16, 16, __half, wmma::row_major> ah, alo;
        wmma::load_matrix_sync(ah,  xh + rt * 16 * LDH + k * 16, LDH);
        wmma::load_matrix_sync(alo, xl + rt * 16 * LDH + k * 16, LDH);
        #pragma unroll
        for (int j = 0; j < 4; j++) {
            wmma::fragment<wmma::matrix_b, 16, 16, 16, __half, wmma::row_major> bh, blo;
            wmma::load_matrix_sync(bh,  wh + k * 16 * LDH + c0 + j * 16, LDH);
            wmma::load_matrix_sync(blo, wl + k * 16 * LDH + c0 + j * 16, LDH);
            wmma::mma_sync(acc[j], ah,  bh,  acc[j]);
            wmma::mma_sync(acc[j], ah,  blo, acc[j]);
            wmma::mma_sync(acc[j], alo, bh,  acc[j]);
        }
    }
    __syncthreads();   // all warps done reading xh/xl before overwrite as C

    #pragma unroll
    for (int j = 0; j < 4; j++)
        wmma::store_matrix_sync(Cs + rt * 16 * LDC + c0 + j * 16, acc[j], LDC,
                                wmma::mem_row_major);
    __syncthreads();

    // epilogue: warp owns 8 rows (all 128 cols across 32 lanes x 4 cols)
    int lane = t & 31;
    int cj = lane * 4;
    int r0 = w * 8;
    float4 a4 = make_float4(0.f, 0.f, 0.f, 0.f), r4 = a4;
    if (al != nullptr) {
        a4 = ((const float4*)al)[lane];
        r4 = ((const float4*)ar)[lane];
    }
    #pragma unroll
    for (int r = 0; r < 8; r++) {
        int row = row0 + r0 + r;
        float4 v;
        v.x = Cs[(r0 + r) * LDC + cj + 0];
        v.y = Cs[(r0 + r) * LDC + cj + 1];
        v.z = Cs[(r0 + r) * LDC + cj + 2];
        v.w = Cs[(r0 + r) * LDC + cj + 3];
        if (row < nrows) {
            if (Yh) {
                __half2 p0 = __floats2half2_rn(v.x, v.y);
                __half2 p1 = __floats2half2_rn(v.z, v.w);
                unsigned u0 = *(unsigned*)&p0;
                unsigned u1 = *(unsigned*)&p1;
                ((uint2*)Yh)[(size_t)row * 32 + lane] = make_uint2(u0, u1);
            }
            if (Yf)
                *(float4*)(Yf + (size_t)row * 128 + cj) = v;
        }
        if (al != nullptr) {
            float pl = v.x * a4.x + v.y * a4.y + v.z * a4.z + v.w * a4.w;
            float pr = v.x * r4.x + v.y * r4.y + v.z * r4.z + v.w * r4.w;
            #pragma unroll
            for (int o = 16; o; o >>= 1) {
                pl += __shfl_xor_sync(0xffffffffu, pl, o);
                pr += __shfl_xor_sync(0xffffffffu, pr, o);
            }
            if (lane == 0 && row < nrows) { g_el[row] = pl; g_er[row] = pr; }
        }
    }
}

// ---------------- fused softmax-attention + aggregation, one warp per dst node ----------------
// 2-pass max-free softmax: scores bounded (|e| << 80) so exp(e) is fp32-safe and
// the normalized result is algebraically identical to the max-subtracted form.
__global__ void k_node(const float* __restrict__ bvec, int do_relu) {
    int gw = (blockIdx.x * blockDim.x + threadIdx.x) >> 5;
    int lane = threadIdx.x & 31;
    if (gw >= N_NODES) return;
    int start = g_rowptr[gw];
    int end   = g_rowptr[gw + 1];
    float eld = g_el[gw];

    // pass A: exp(score) + segment sum (one MUFU per lane-edge)
    float ssum = 0.f;
    for (int i = start + lane; i < end; i += 32) {
        int s = g_esrc[i];
        float e = eld + g_er[s];
        e = (e > 0.f) ? e : 0.2f * e;     // leaky_relu 0.2
        float p = __expf(e);
        g_ebuf[i] = p;
        ssum += p;
    }
    #pragma unroll
    for (int o = 16; o; o >>= 1) ssum += __shfl_xor_sync(0xffffffffu, ssum, o);
    float inv = 1.f / (ssum + 1e-10f);
    __syncwarp();   // make cross-lane g_ebuf writes visible

    // pass B: weighted fp16 gather; lane owns 4 contiguous cols; no MUFU here
    float4 acc = make_float4(0.f, 0.f, 0.f, 0.f);
    const uint2* H2 = (const uint2*)g_Hh;
    #pragma unroll 4
    for (int i = start; i < end; i++) {
        float a = g_ebuf[i] * inv;        // broadcast load, precomputed exp
        int s = g_esrc[i];                // broadcast load
        uint2 raw = H2[(size_t)s * 32 + lane];
        __half2 h0 = *(__half2*)&raw.x;
        __half2 h1 = *(__half2*)&raw.y;
        float2 f0 = __half22float2(h0);
        float2 f1 = __half22float2(h1);
        acc.x += a * f0.x; acc.y += a * f0.y;
        acc.z += a * f1.x; acc.w += a * f1.y;
    }

    float4 b4 = ((const float4*)bvec)[lane];
    float4 o4 = make_float4(acc.x + b4.x, acc.y + b4.y, acc.z + b4.z, acc.w + b4.w);
    if (do_relu) {
        o4.x = fmaxf(o4.x, 0.f); o4.y = fmaxf(o4.y, 0.f);
        o4.z = fmaxf(o4.z, 0.f); o4.w = fmaxf(o4.w, 0.f);
    }
    ((float4*)g_X)[(size_t)gw * 32 + lane] = o4;
}

// ---------------- bilinear head: scores[m][s] = dot(T[m], server[s]) + bb ----------------
__global__ void k_scores(const float* __restrict__ bb, float* __restrict__ out) {
    __shared__ __align__(16) float Tm[16][132];
    __shared__ __align__(16) float Ss[16][132];
    int tx = threadIdx.x;       // s within tile
    int ty = threadIdx.y;       // m within tile
    int m0 = blockIdx.x * 16, s0 = blockIdx.y * 16;
    int t = ty * 16 + tx;
    for (int i = t; i < 512; i += 256) {
        int r = i >> 5, c = i & 31;
        float4 v = ((const float4*)g_T)[(size_t)(m0 + r) * 32 + c];
        *(float4*)&Tm[r][c * 4] = v;
        float4 w = ((const float4*)g_X)[(size_t)(NUC + NMC + s0 + r) * 32 + c];
        *(float4*)&Ss[r][c * 4] = w;
    }
    __syncthreads();
    float4 acc = make_float4(0.f, 0.f, 0.f, 0.f);
    #pragma unroll 8
    for (int k = 0; k < 32; k++) {
        float4 a = *(const float4*)&Tm[ty][k * 4];
        float4 b = *(const float4*)&Ss[tx][k * 4];
        acc.x += a.x * b.x; acc.y += a.y * b.y;
        acc.z += a.z * b.z; acc.w += a.w * b.w;
    }
    out[(m0 + ty) * NSC + (s0 + tx)] = acc.x + acc.y + acc.z + acc.w + bb[0];
}

// ---------------- host ----------------
extern "C" void kernel_launch(void* const* d_in, const int* in_sizes, int n_in,
                              void* d_out, int out_size) {
    const float* x   = (const float*)d_in[0];
    const int*   ei  = (const int*)  d_in[1];
    const int*   src = ei;
    const int*   dst = ei + NEDGE;
    const float* W1  = (const float*)d_in[2];
    const float* al1 = (const float*)d_in[3];
    const float* ar1 = (const float*)d_in[4];
    const float* b1  = (const float*)d_in[5];
    const float* W2  = (const float*)d_in[6];
    const float* al2 = (const float*)d_in[7];
    const float* ar2 = (const float*)d_in[8];
    const float* b2  = (const float*)d_in[9];
    const float* W3  = (const float*)d_in[10];
    const float* al3 = (const float*)d_in[11];
    const float* ar3 = (const float*)d_in[12];
    const float* b3  = (const float*)d_in[13];
    const float* Wb  = (const float*)d_in[14];
    const float* bb  = (const float*)d_in[15];
    float* out = (float*)d_out;

    void *pX_, *pHh_, *pT_;
    cudaGetSymbolAddress(&pX_, g_X);
    cudaGetSymbolAddress(&pHh_, g_Hh);
    cudaGetSymbolAddress(&pT_, g_T);
    float*  pX = (float*)pX_;
    __half* pH = (__half*)pHh_;
    float*  pT = (float*)pT_;

    const int smem_bytes = 384 * LDH * 2;   // xh+xl (64 each) + wh+wl (128 each) = 104448 B
    cudaFuncSetAttribute(k_gemm, cudaFuncAttributeMaxDynamicSharedMemorySize, smem_bytes);

    int warpgrid = (N_NODES * 32 + 255) / 256;
    int gemmgrid = (N_NODES + 63) / 64;

    // CSR build; gemm layer-1 hoisted to launch index 3 so ncu (-s => idx 3)
    // profiles the GEMM. (Single stream: ordering is purely for profiling.)
    k_count  <<<(NEDGE / 4 + 255) / 256, 256>>>(dst);                           // 0
    k_scan1  <<<NB, 256>>>();                                                   // 1
    k_scan2  <<<1, 256>>>();                                                    // 2
    k_gemm<<<gemmgrid, 256, smem_bytes>>>(x, W1, nullptr, pH, N_NODES, al1, ar1); // 3 (profiled)
    k_scan3  <<<NB, 256>>>();                                                   // 4
    k_scatter<<<(NEDGE / 4 + 255) / 256, 256>>>(src, dst);                      // 5

    // layer 1 aggregation
    k_node<<<warpgrid, 256>>>(b1, 1);
    // layer 2
    k_gemm<<<gemmgrid, 256, smem_bytes>>>(pX, W2, nullptr, pH, N_NODES, al2, ar2);
    k_node<<<warpgrid, 256>>>(b2, 1);
    // layer 3 (no relu)
    k_gemm<<<gemmgrid, 256, smem_bytes>>>(pX, W3, nullptr, pH, N_NODES, al3, ar3);
    k_node<<<warpgrid, 256>>>(b3, 0);

    // bilinear head
    k_gemm<<<(NMC + 63) / 64, 256, smem_bytes>>>(pX + (size_t)NUC * HDIM, Wb, pT, nullptr, NMC,
                                                 nullptr, nullptr);
    k_scores<<<dim3(NMC / 16, NSC / 16), dim3(16, 16)>>>(bb, out);
}